// round 2
// baseline (speedup 1.0000x reference)
#include <cuda_runtime.h>

typedef unsigned long long ull;

#define SEQ   256
#define BSZ   2048
#define FDIM  5
#define HDIM  64
#define KAUX  8
#define NCOL  1280           // 256 (main gates) + 8*128 (aux gates)
#define BT    8              // batch rows per block
#define NTHR  256
#define NBLK  (BSZ / BT)     // 256  -> 2 blocks per SM on the loaded SMs

// ---------------- repacked weights (device globals; prep kernel fills) ------
__device__ __align__(16) float g_Ucat[HDIM * NCOL];   // [h][col] recurrent cat
__device__ __align__(16) float g_Wx[FDIM * NCOL];     // [f][col] input proj cat
__device__ __align__(16) float g_bcat[NCOL];          // bias cat
__device__ __align__(16) float g_W2[128 * 256];       // [h<64:Wih^T, h>=64:Whh^T][j]
__device__ __align__(16) float g_b2[256];             // b_ih + b_hh
__device__ __align__(16) float g_WattP[HDIM * HDIM];  // [g][2l]=(Watt[l][g],Watt[l+32][g])
__device__ __align__(16) float g_linW[HDIM];

// ---------------- f32x2 helpers (FFMA2 path, sm_100+) -----------------------
__device__ __forceinline__ void fma2(ull &d, ull a, ull b) {
    asm("fma.rn.f32x2 %0, %1, %2, %0;" : "+l"(d) : "l"(a), "l"(b));
}
__device__ __forceinline__ void upk(ull v, float &lo, float &hi) {
    asm("mov.b64 {%0,%1}, %2;" : "=f"(lo), "=f"(hi) : "l"(v));
}

// ---------------- fast activations (fp32, ~1e-6 error) ----------------------
__device__ __forceinline__ float fsig(float x) {
    float e = __expf(-x);
    return __fdividef(1.f, 1.f + e);
}
__device__ __forceinline__ float ftanh(float x) {
    return 2.f * fsig(2.f * x) - 1.f;
}

// ---------------- prep: repack weights --------------------------------------
__global__ void prep_kernel(const float *__restrict__ Wm, const float *__restrict__ Um,
                            const float *__restrict__ bm, const float *__restrict__ Wa,
                            const float *__restrict__ Ua, const float *__restrict__ ba,
                            const float *__restrict__ Watt, const float *__restrict__ Wih,
                            const float *__restrict__ Whh, const float *__restrict__ bih,
                            const float *__restrict__ bhh, const float *__restrict__ linW) {
    int i = blockIdx.x * blockDim.x + threadIdx.x;
    if (i < HDIM * NCOL) {
        int h = i / NCOL, col = i % NCOL;
        float v;
        if (col < 256) v = Um[h * 256 + col];
        else { int cc = col - 256; int k = cc >> 7, j = cc & 127; v = Ua[(k * HDIM + h) * 128 + j]; }
        g_Ucat[i] = v;
    }
    if (i < FDIM * NCOL) {
        int f = i / NCOL, col = i % NCOL;
        float v;
        if (col < 256) v = Wm[f * 256 + col];
        else { int cc = col - 256; int k = cc >> 7, j = cc & 127; v = Wa[(k * FDIM + f) * 128 + j]; }
        g_Wx[i] = v;
    }
    if (i < NCOL) g_bcat[i] = (i < 256) ? bm[i] : ba[i - 256];
    if (i < 128 * 256) {
        int h = i / 256, j = i % 256;
        g_W2[i] = (h < 64) ? Wih[j * 64 + h] : Whh[j * 64 + (h - 64)];
    }
    if (i < 256) g_b2[i] = bih[i] + bhh[i];
    if (i < HDIM * HDIM) {
        // WattP[g][2l+p] = Watt[l + 32p][g]
        int g = i >> 6, q = i & 63, l = q >> 1, p = q & 1;
        g_WattP[i] = Watt[(l + 32 * p) * HDIM + g];
    }
    if (i < HDIM) g_linW[i] = linW[i];
}

// ---------------- smem layout (floats) --------------------------------------
#define SM_G    0                       // G[8][1280]             10240
#define SM_G2   10240                   // g2[8][256]              2048
#define SM_HD   12288                   // hd[8][128] dup f2       2048
#define SM_CD   14336                   // cd[8][64] dup f2        1024
#define SM_XD   15360                   // xd[9][5][8] dup f2       720
#define SM_WX   16080                   // Wx copy                 6400
#define SM_BC   22480                   // bcat copy               1280
#define SM_WP   23760                   // WattP copy              4096
#define SM_B2   27856                   // b2 copy                  256
#define SM_LW   28112                   // linW copy                 64
#define SM_TOT  28176                   // 112704 bytes

__global__ void __launch_bounds__(NTHR, 2)
mi_kernel(const float *__restrict__ Y,
          const float *__restrict__ X1, const float *__restrict__ X2,
          const float *__restrict__ X3, const float *__restrict__ X4,
          const float *__restrict__ X5, const float *__restrict__ X6,
          const float *__restrict__ X7, const float *__restrict__ X8,
          const float *__restrict__ batt_p, const float *__restrict__ linb_p,
          float *__restrict__ out) {
    extern __shared__ float sm[];
    float *sG  = sm + SM_G;
    float *sG2 = sm + SM_G2;
    float *sHD = sm + SM_HD;
    float *sCD = sm + SM_CD;
    float *sXD = sm + SM_XD;
    float *sWX = sm + SM_WX;
    float *sBC = sm + SM_BC;
    float *sWP = sm + SM_WP;
    float *sB2 = sm + SM_B2;
    float *sLW = sm + SM_LW;

    const int tid  = threadIdx.x;
    const int warp = tid >> 5, lane = tid & 31;
    const int rg = tid >> 7;          // 0..1  -> rows 4rg..4rg+3
    const int cg = tid & 127;         // col pair (2cg,2cg+1) per 256-col segment
    const int b0 = blockIdx.x * BT;

    const float batt = *batt_p;
    const float linb = *linb_p;
    const float *xp[9] = {Y, X1, X2, X3, X4, X5, X6, X7, X8};

    // copy reused small weights into smem; zero state
    for (int i = tid; i < FDIM * NCOL; i += NTHR) sWX[i] = g_Wx[i];
    for (int i = tid; i < NCOL; i += NTHR)        sBC[i] = g_bcat[i];
    for (int i = tid; i < HDIM * HDIM; i += NTHR) sWP[i] = g_WattP[i];
    for (int i = tid; i < 256; i += NTHR)         sB2[i] = g_b2[i];
    for (int i = tid; i < HDIM; i += NTHR)        sLW[i] = g_linW[i];
    for (int i = tid; i < BT * 128 * 2; i += NTHR) sHD[i] = 0.f;
    for (int i = tid; i < BT * 64 * 2; i += NTHR)  sCD[i] = 0.f;

    float c1a = 0.f, c1b = 0.f;   // phase-1 cell (lane, lane+32) of row `warp`
    float c2a = 0.f, c2b = 0.f;   // phase-2 cell

    // column segments of this thread
    int cols[5], srcs[5];
#pragma unroll
    for (int i = 0; i < 5; i++) {
        cols[i] = 2 * cg + 256 * i;
        srcs[i] = (i == 0) ? 0 : 1 + (i - 1) * 2 + (cg >> 6);
    }

    // stage inputs for t=0 (pre-duplicated)
    {
        size_t base = (size_t)b0 * FDIM;
        for (int j = tid; j < 9 * BT * FDIM; j += NTHR) {
            int s = j / (BT * FDIM), rem = j - s * (BT * FDIM);
            int row = rem / FDIM, f = rem - row * FDIM;
            float v = xp[s][base + rem];
            int o = ((s * FDIM + f) * BT + row) * 2;
            sXD[o] = v; sXD[o + 1] = v;
        }
    }
    __syncthreads();

    float pv0 = 0.f, pv1 = 0.f;   // next-step input prefetch

    for (int t = 0; t < SEQ; t++) {
        // ================= phase-1 GEMM: G = b + x@Wx + h1@Ucat ==============
        {
            ull acc[4][5];
#pragma unroll
            for (int i = 0; i < 5; i++) {
                ull bp = *(const ull *)&sBC[cols[i]];
                acc[0][i] = bp; acc[1][i] = bp; acc[2][i] = bp; acc[3][i] = bp;
            }
#pragma unroll
            for (int f = 0; f < FDIM; f++) {
#pragma unroll
                for (int i = 0; i < 5; i++) {
                    ull w = *(const ull *)&sWX[f * NCOL + cols[i]];
                    int s = srcs[i];
#pragma unroll
                    for (int r = 0; r < 4; r++) {
                        ull xd = *(const ull *)&sXD[((s * FDIM + f) * BT + 4 * rg + r) * 2];
                        fma2(acc[r][i], xd, w);
                    }
                }
            }
#pragma unroll 4
            for (int h = 0; h < HDIM; h++) {
                ull hd[4];
#pragma unroll
                for (int r = 0; r < 4; r++)
                    hd[r] = *(const ull *)&sHD[((4 * rg + r) * 128 + h) * 2];
#pragma unroll
                for (int i = 0; i < 5; i++) {
                    ull w = *(const ull *)&g_Ucat[h * NCOL + cols[i]];
#pragma unroll
                    for (int r = 0; r < 4; r++) fma2(acc[r][i], hd[r], w);
                }
            }
#pragma unroll
            for (int r = 0; r < 4; r++)
#pragma unroll
                for (int i = 0; i < 5; i++)
                    *(ull *)&sG[(4 * rg + r) * NCOL + cols[i]] = acc[r][i];
        }
        __syncthreads();

        // ========== phase-1 elementwise + attention (warp r = row r) =========
        {
            const int r = warp;
            const float *Gr = &sG[r * NCOL];
            const int h0 = lane, h1 = lane + 32;

            float i0 = fsig(Gr[h0]),        i1 = fsig(Gr[h1]);
            float f0 = fsig(Gr[64 + h0]),   f1 = fsig(Gr[64 + h1]);
            float o0 = fsig(Gr[128 + h0]),  o1 = fsig(Gr[128 + h1]);
            float m0 = ftanh(Gr[192 + h0]), m1 = ftanh(Gr[192 + h1]);

            float l0[9], l1[9];
            l0[0] = i0 * m0; l1[0] = i1 * m1;
#pragma unroll
            for (int k = 0; k < KAUX; k++) {
                const float *Ga = Gr + 256 + 128 * k;
                l0[k + 1] = fsig(Ga[h0]) * ftanh(Ga[64 + h0]);
                l1[k + 1] = fsig(Ga[h1]) * ftanh(Ga[64 + h1]);
            }

            // v = W_att @ c_prev  (FFMA2: dup'd c × paired W_att)
            ull vacc = 0ull;
#pragma unroll 8
            for (int g = 0; g < HDIM; g++)
                fma2(vacc, *(const ull *)&sCD[(r * HDIM + g) * 2],
                           *(const ull *)&sWP[g * HDIM + 2 * lane]);
            float v0, v1; upk(vacc, v0, v1);

            // u_k = tanh(l_k . v + b_att); softmax (u in (-1,1): no max shift)
            float e[9], esum = 0.f;
#pragma unroll
            for (int k = 0; k < 9; k++) {
                float d = l0[k] * v0 + l1[k] * v1;
                d += __shfl_xor_sync(0xffffffffu, d, 16);
                d += __shfl_xor_sync(0xffffffffu, d, 8);
                d += __shfl_xor_sync(0xffffffffu, d, 4);
                d += __shfl_xor_sync(0xffffffffu, d, 2);
                d += __shfl_xor_sync(0xffffffffu, d, 1);
                e[k] = __expf(ftanh(d + batt));
                esum += e[k];
            }
            float inv = __fdividef(1.f, esum);
            float L0 = 0.f, L1 = 0.f;
#pragma unroll
            for (int k = 0; k < 9; k++) {
                float a = e[k] * inv;
                L0 = fmaf(a, l0[k], L0);
                L1 = fmaf(a, l1[k], L1);
            }
            float cn0 = fmaf(f0, c1a, L0), cn1 = fmaf(f1, c1b, L1);
            float hn0 = o0 * ftanh(cn0),   hn1 = o1 * ftanh(cn1);
            c1a = cn0; c1b = cn1;
            __syncwarp();                              // matvec reads of sCD done
            int oc0 = (r * HDIM + h0) * 2, oc1 = (r * HDIM + h1) * 2;
            sCD[oc0] = cn0; sCD[oc0 + 1] = cn0;
            sCD[oc1] = cn1; sCD[oc1 + 1] = cn1;
            int oh0 = (r * 128 + h0) * 2, oh1 = (r * 128 + h1) * 2;
            sHD[oh0] = hn0; sHD[oh0 + 1] = hn0;
            sHD[oh1] = hn1; sHD[oh1 + 1] = hn1;
        }
        __syncthreads();

        // ====== phase-2 GEMM: g2 = b2 + [h1_cur; h2_prev] @ [Wih^T;Whh^T] ====
        {
            // prefetch next-step inputs (hidden behind the GEMM)
            if (t + 1 < SEQ) {
                size_t base = (size_t)(t + 1) * BSZ * FDIM + (size_t)b0 * FDIM;
                int j0 = tid, j1 = tid + NTHR;
                if (j0 < 360) { int s = j0 / 40; pv0 = xp[s][base + (j0 - s * 40)]; }
                if (j1 < 360) { int s = j1 / 40; pv1 = xp[s][base + (j1 - s * 40)]; }
            }

            ull acc2[4];
            ull bp = *(const ull *)&sB2[2 * cg];
            acc2[0] = bp; acc2[1] = bp; acc2[2] = bp; acc2[3] = bp;
#pragma unroll 4
            for (int h = 0; h < 128; h++) {
                ull w = *(const ull *)&g_W2[h * 256 + 2 * cg];
#pragma unroll
                for (int r = 0; r < 4; r++)
                    fma2(acc2[r], *(const ull *)&sHD[((4 * rg + r) * 128 + h) * 2], w);
            }
#pragma unroll
            for (int r = 0; r < 4; r++)
                *(ull *)&sG2[(4 * rg + r) * 256 + 2 * cg] = acc2[r];
        }
        __syncthreads();

        // ======= phase-2 elementwise + head; store prefetched inputs =========
        {
            const int r = warp;
            const float *gr = &sG2[r * 256];
            const int j0 = lane, j1 = lane + 32;
            float i0 = fsig(gr[j0]),         i1 = fsig(gr[j1]);
            float f0 = fsig(gr[64 + j0]),    f1 = fsig(gr[64 + j1]);
            float gg0 = ftanh(gr[128 + j0]), gg1 = ftanh(gr[128 + j1]);
            float o0 = fsig(gr[192 + j0]),   o1 = fsig(gr[192 + j1]);
            c2a = fmaf(f0, c2a, i0 * gg0);
            c2b = fmaf(f1, c2b, i1 * gg1);
            float h20 = o0 * ftanh(c2a), h21 = o1 * ftanh(c2b);
            int o0i = (r * 128 + 64 + j0) * 2, o1i = (r * 128 + 64 + j1) * 2;
            sHD[o0i] = h20; sHD[o0i + 1] = h20;
            sHD[o1i] = h21; sHD[o1i + 1] = h21;
            float ov = fmaxf(h20, 0.f) * sLW[j0] + fmaxf(h21, 0.f) * sLW[j1];
            ov += __shfl_xor_sync(0xffffffffu, ov, 16);
            ov += __shfl_xor_sync(0xffffffffu, ov, 8);
            ov += __shfl_xor_sync(0xffffffffu, ov, 4);
            ov += __shfl_xor_sync(0xffffffffu, ov, 2);
            ov += __shfl_xor_sync(0xffffffffu, ov, 1);
            if (lane == 0) out[(size_t)t * BSZ + b0 + r] = ov + linb;

            // stage prefetched inputs (dup'd) for t+1
            if (t + 1 < SEQ) {
                int j = tid;
                if (j < 360) {
                    int s = j / 40, rem = j - s * 40;
                    int row = rem / FDIM, f = rem - row * FDIM;
                    int o = ((s * FDIM + f) * BT + row) * 2;
                    sXD[o] = pv0; sXD[o + 1] = pv0;
                }
                j = tid + NTHR;
                if (j < 360) {
                    int s = j / 40, rem = j - s * 40;
                    int row = rem / FDIM, f = rem - row * FDIM;
                    int o = ((s * FDIM + f) * BT + row) * 2;
                    sXD[o] = pv1; sXD[o + 1] = pv1;
                }
            }
        }
        __syncthreads();
    }
}

// ---------------- launch ----------------------------------------------------
extern "C" void kernel_launch(void *const *d_in, const int *in_sizes, int n_in,
                              void *d_out, int out_size) {
    (void)in_sizes; (void)n_in; (void)out_size;
    const float *Y    = (const float *)d_in[0];
    const float *x1   = (const float *)d_in[1];
    const float *x2   = (const float *)d_in[2];
    const float *x3   = (const float *)d_in[3];
    const float *x4   = (const float *)d_in[4];
    const float *x5   = (const float *)d_in[5];
    const float *x6   = (const float *)d_in[6];
    const float *x7   = (const float *)d_in[7];
    const float *x8   = (const float *)d_in[8];
    const float *Wm   = (const float *)d_in[9];
    const float *Um   = (const float *)d_in[10];
    const float *bm   = (const float *)d_in[11];
    const float *Wa   = (const float *)d_in[12];
    const float *Ua   = (const float *)d_in[13];
    const float *ba   = (const float *)d_in[14];
    const float *Watt = (const float *)d_in[15];
    const float *batt = (const float *)d_in[16];
    const float *Wih  = (const float *)d_in[17];
    const float *Whh  = (const float *)d_in[18];
    const float *bih  = (const float *)d_in[19];
    const float *bhh  = (const float *)d_in[20];
    const float *linW = (const float *)d_in[21];
    const float *linb = (const float *)d_in[22];
    float *out = (float *)d_out;

    prep_kernel<<<(HDIM * NCOL + 255) / 256, 256>>>(Wm, Um, bm, Wa, Ua, ba, Watt,
                                                    Wih, Whh, bih, bhh, linW);

    cudaFuncSetAttribute(mi_kernel, cudaFuncAttributeMaxDynamicSharedMemorySize,
                         SM_TOT * (int)sizeof(float));
    mi_kernel<<<NBLK, NTHR, SM_TOT * sizeof(float)>>>(Y, x1, x2, x3, x4, x5, x6, x7, x8,
                                                      batt, linb, out);
}